// round 16
// baseline (speedup 1.0000x reference)
#include <cuda_runtime.h>
#include <math_constants.h>

#define B_DIM 8
#define S_DIM 4096
#define H_DIM 1024
#define N_SPANS 100
#define TOTAL_SPANS (B_DIM * N_SPANS)     // 800
#define MAX_LEN 64

#define W (H_DIM / 4)         // 256 float4 lanes per row
#define NGROUPS 4
#define NTHREADS (NGROUPS * W)  // 1024: 4 row-groups x 256 column lanes

__device__ __forceinline__ float4 fmax4(float4 a, float4 b) {
    float4 r;
    r.x = fmaxf(a.x, b.x);
    r.y = fmaxf(a.y, b.y);
    r.z = fmaxf(a.z, b.z);
    r.w = fmaxf(a.w, b.w);
    return r;
}

__global__ __launch_bounds__(NTHREADS)
void maxpool_span_kernel(const float* __restrict__ ctx,
                         const int* __restrict__ begins,
                         const int* __restrict__ lens,
                         float* __restrict__ out) {
    // Partials from groups 1..3: 3 x 256 x float4 = 12 KB
    __shared__ float4 s_part[(NGROUPS - 1) * W];

    const int span = blockIdx.x;             // 0 .. 799
    const int b    = span / N_SPANS;

    const int tid = threadIdx.x;
    const int col = tid & (W - 1);           // 0..255  (float4 column)
    const int grp = tid >> 8;                // 0..3    (row quarter)

    // Metadata loads issue together; same address CTA-wide -> broadcast.
    const int begin = __ldg(&begins[span]);
    int len = __ldg(&lens[span]);
    len = len < 1 ? 1 : len;

    // Balanced 4-way split: q = len/4, remainder r to the first r groups.
    // Quantum <= 16 rows  =>  at most 2 MLP-8 rounds per group.
    const int q = len >> 2;
    const int r = len & 3;
    const int rows  = q + (grp < r ? 1 : 0);     // may be 0 for len < 4
    const int start = grp * q + min(grp, r);

    const float4* base = (const float4*)(ctx + (long long)b * S_DIM * H_DIM
                             + (long long)(begin + start) * H_DIM) + col;

    const float NEG = -CUDART_INF_F;
    float4 m0 = make_float4(NEG, NEG, NEG, NEG);
    float4 m1 = m0, m2 = m0, m3 = m0;

    int p = 0;
    // 8 independent outstanding 16B loads per thread per round (MLP = 8)
    for (; p + 8 <= rows; p += 8) {
        float4 v0 = __ldg(base + (p + 0) * W);
        float4 v1 = __ldg(base + (p + 1) * W);
        float4 v2 = __ldg(base + (p + 2) * W);
        float4 v3 = __ldg(base + (p + 3) * W);
        float4 v4 = __ldg(base + (p + 4) * W);
        float4 v5 = __ldg(base + (p + 5) * W);
        float4 v6 = __ldg(base + (p + 6) * W);
        float4 v7 = __ldg(base + (p + 7) * W);
        m0 = fmax4(m0, fmax4(v0, v4));
        m1 = fmax4(m1, fmax4(v1, v5));
        m2 = fmax4(m2, fmax4(v2, v6));
        m3 = fmax4(m3, fmax4(v3, v7));
    }
    if (p + 4 <= rows) {
        float4 v0 = __ldg(base + (p + 0) * W);
        float4 v1 = __ldg(base + (p + 1) * W);
        float4 v2 = __ldg(base + (p + 2) * W);
        float4 v3 = __ldg(base + (p + 3) * W);
        m0 = fmax4(m0, v0);
        m1 = fmax4(m1, v1);
        m2 = fmax4(m2, v2);
        m3 = fmax4(m3, v3);
        p += 4;
    }
    for (; p < rows; p++) {
        m0 = fmax4(m0, __ldg(base + p * W));
    }

    m0 = fmax4(m0, m1);
    m2 = fmax4(m2, m3);
    m0 = fmax4(m0, m2);

    // Combine: groups 1..3 publish partials (identity -inf when their quarter
    // is empty — branchless). Group 0 merges and does ONE coalesced store.
    if (grp) {
        s_part[(grp - 1) * W + col] = m0;
    }
    __syncthreads();
    if (!grp) {
        float4 a = s_part[0 * W + col];
        float4 c = s_part[1 * W + col];
        float4 d = s_part[2 * W + col];
        m0 = fmax4(fmax4(m0, a), fmax4(c, d));
        float4* o = (float4*)(out + (long long)span * H_DIM) + col;
        *o = m0;
    }
}

extern "C" void kernel_launch(void* const* d_in, const int* in_sizes, int n_in,
                              void* d_out, int out_size) {
    const float* ctx    = (const float*)d_in[0];   // [B, S, H] float32
    const int*   begins = (const int*)d_in[1];     // [B, N_SPANS] int32
    const int*   lens   = (const int*)d_in[2];     // [B, N_SPANS] int32
    float* out = (float*)d_out;                    // [B, N_SPANS, H] float32

    // No init pass, no atomics: each span's CTA produces the final value
    // and writes it with a single plain store.
    maxpool_span_kernel<<<TOTAL_SPANS, NTHREADS>>>(ctx, begins, lens, out);
}